// round 9
// baseline (speedup 1.0000x reference)
#include <cuda_runtime.h>
#include <cstdint>

// ---------------------------------------------------------------------------
// Reference constants. Host constexpr copies (compile-time table generation)
// and __device__ copies (exact fallback path). Host constexpr fp32 +/-/* is
// IEEE RN => bit-identical to device FADD/FMUL.
// ---------------------------------------------------------------------------
constexpr float HH[16] = {
    -0.00443981f, 0.0244156f, -0.01410327f, 0.01784681f,
    -0.00239246f, 0.06331808f, 0.01457577f, 0.01753613f,
     0.01339214f, -0.0131252f, 0.02026613f, 0.00109124f,
    -0.01996419f, 0.00723148f, 0.03052537f, -0.00465259f};
constexpr float DDc[16] = {
    -0.04305673f, 2.0701091e-05f, -0.028386816f, 0.065610707f,
     0.071529418f, -0.0010542608f, 0.0012044241f, 0.00077212957f,
    -0.00072495628f, 0.0010990113f, 0.00087419833f, -0.0031887756f,
    -0.019837018f, 0.00030188679f, 0.00022616754f, -0.0017746047f};
constexpr float TTc[16] = {
    -0.1190194f, 0.03273299f, -0.05586114f, 0.07758415f,
    -0.06072911f, 0.04350465f, -0.06501344f, -0.07967568f,
    -0.08437239f, -0.07040057f, -0.07470815f, 0.01298669f,
     0.12695177f, 0.00617064f, -0.08909994f, 0.05016604f};

__device__ constexpr float cH[16] = {
    -0.00443981f, 0.0244156f, -0.01410327f, 0.01784681f,
    -0.00239246f, 0.06331808f, 0.01457577f, 0.01753613f,
     0.01339214f, -0.0131252f, 0.02026613f, 0.00109124f,
    -0.01996419f, 0.00723148f, 0.03052537f, -0.00465259f};
__device__ constexpr float cD[16] = {
    -0.04305673f, 2.0701091e-05f, -0.028386816f, 0.065610707f,
     0.071529418f, -0.0010542608f, 0.0012044241f, 0.00077212957f,
    -0.00072495628f, 0.0010990113f, 0.00087419833f, -0.0031887756f,
    -0.019837018f, 0.00030188679f, 0.00022616754f, -0.0017746047f};
__device__ constexpr float cT[16] = {
    -0.1190194f, 0.03273299f, -0.05586114f, 0.07758415f,
    -0.06072911f, 0.04350465f, -0.06501344f, -0.07967568f,
    -0.08437239f, -0.07040057f, -0.07470815f, 0.01298669f,
     0.12695177f, 0.00617064f, -0.08909994f, 0.05016604f};

// All-fire output in the reference's fp32 accumulation order.
constexpr float DSUM_C =
    (((((((((((((((-0.04305673f
      + 2.0701091e-05f) + -0.028386816f) + 0.065610707f) + 0.071529418f)
      + -0.0010542608f) + 0.0012044241f) + 0.00077212957f) + -0.00072495628f)
      + 0.0010990113f) + 0.00087419833f) + -0.0031887756f) + -0.019837018f)
      + 0.00030188679f) + 0.00022616754f) + -0.0017746047f);

constexpr int   NBUCKETS = 2048;
constexpr float KSCALE   = 2048.0f / 0.26f;   // all-fire for |x| >= 0.26
constexpr float SENTF    = 1e30f;             // sentinel (|outputs| < 1)

// Exact per-element trajectory (bit-identical to reference; rel_err==0
// since R0). (v-T)/(|v|+1) > 0 <=> v > T ; step 0 always fires (T[0]<0<=|x|).
__device__ __forceinline__ float snn_elem(float x) {
    float v = fabsf(x);
    float out = cD[0];
    v -= cH[1];
    bool z = v > cT[1];
    if (z) out += cD[1];
#pragma unroll
    for (int t = 2; t < 16; ++t) {
        if (z) v -= cH[t];
        z = v > cT[t];
        if (z) out += cD[t];
    }
    float r = (x > 0.0f) ? out : -out;
    return (x == 0.0f) ? 0.0f : r;
}

// ---------------------------------------------------------------------------
// Compile-time table. Bucket i covers u with trunc(fl(u*KSCALE)) == i.
// Endpoints widened by 1e-6 relative (covers the <=2^-24 slack of the fp32
// index product). fp32 monotonicity of the chain => equal firing patterns at
// both ends imply a constant, bit-exact output across the bucket; mismatch
// -> SENTF -> exact per-element fallback. (Validated rel_err==0 in R4-R8.)
// ---------------------------------------------------------------------------
constexpr unsigned snn_pat_ce(float u, float& out) {
    float v = u;
    out = DDc[0];
    unsigned mask = 1u;
    v -= HH[1];
    bool z = v > TTc[1];
    if (z) { out += DDc[1]; mask |= 2u; }
    for (int t = 2; t < 16; ++t) {
        if (z) v -= HH[t];
        z = v > TTc[t];
        if (z) { out += DDc[t]; mask |= (1u << t); }
    }
    return mask;
}

struct alignas(16) Table { float v[2052]; };

constexpr Table make_table() {
    Table tb{};
    tb.v[0] = SENTF;                          // bucket 0 contains x == +-0
    for (int i = 1; i < NBUCKETS; ++i) {
        float lo = (float)((double)i       / (double)KSCALE) * 0.999999f;
        float hi = (float)((double)(i + 1) / (double)KSCALE) * 1.000001f;
        float olo = 0.0f, ohi = 0.0f;
        unsigned mlo = snn_pat_ce(lo, olo);
        unsigned mhi = snn_pat_ce(hi, ohi);
        tb.v[i] = (mlo == mhi) ? olo : SENTF;
    }
    for (int i = NBUCKETS; i < 2052; ++i) tb.v[i] = DSUM_C;  // all-fire + pad
    return tb;
}

__device__ constexpr Table g_tbl = make_table();

// ---------------------------------------------------------------------------
// Main kernels. R8 measured 152.4us @ 81.8% DRAM but regs=37 dropped
// occupancy to 64% (6 blocks/SM). R9: __launch_bounds__(256, 8) caps regs at
// 32 -> 8 blocks/SM; sentinel check aggregated per float4 (one OR-reduce
// instead of 4 ISETP+branches). Plain LDG/STG (R6: .cs hints cost ~4% BW).
// ---------------------------------------------------------------------------
constexpr int THREADS       = 256;
constexpr int VEC_PER_BLOCK = 1024;    // 256 threads x 4 float4

__device__ __forceinline__ void load_table(unsigned* tbl) {
    const float4* src = reinterpret_cast<const float4*>(g_tbl.v);
    float4* dst = reinterpret_cast<float4*>(tbl);
#pragma unroll
    for (int k = 0; k < 3; ++k) {
        int t = threadIdx.x + k * THREADS;
        if (t < 513) dst[t] = src[t];
    }
}

__device__ __forceinline__ void process4(
    const unsigned* tbl, float4 aj, int vi,
    float4* __restrict__ o4, float* __restrict__ out_s) {
    const unsigned sent_bits = __float_as_uint(SENTF);
    const float xs[4] = {aj.x, aj.y, aj.z, aj.w};
    unsigned fb[4], rb[4];
#pragma unroll
    for (int c = 0; c < 4; ++c) {
        int idx = min((int)(fabsf(xs[c]) * KSCALE), NBUCKETS);
        fb[c] = tbl[idx];                     // LDS (~77% hit bucket 2048)
        rb[c] = (__float_as_uint(xs[c]) & 0x80000000u) ^ fb[c];
    }
    o4[vi] = make_float4(__uint_as_float(rb[0]), __uint_as_float(rb[1]),
                         __uint_as_float(rb[2]), __uint_as_float(rb[3]));
    // Aggregated rare-path check: one compare chain + one branch per float4.
    // Sentinel hits recompute exactly and overwrite their own placeholder
    // (same thread, program order).
    unsigned any_sent = (fb[0] == sent_bits) | (fb[1] == sent_bits) |
                        (fb[2] == sent_bits) | (fb[3] == sent_bits);
    if (any_sent) {
#pragma unroll
        for (int c = 0; c < 4; ++c) {
            if (fb[c] == sent_bits) out_s[vi * 4 + c] = snn_elem(xs[c]);
        }
    }
}

// Full blocks, no bounds checks; min-8-blocks forces regs <= 32.
__global__ void __launch_bounds__(THREADS, 8) snn_tbl_full_kernel(
    const float4* __restrict__ x4, float4* __restrict__ o4) {
    __shared__ unsigned tbl[2052];
    load_table(tbl);
    __syncthreads();

    const int base = blockIdx.x * VEC_PER_BLOCK + threadIdx.x;
    float* out_s = (float*)o4;

    float4 a[4];
#pragma unroll
    for (int j = 0; j < 4; ++j) a[j] = x4[base + j * THREADS];
#pragma unroll
    for (int j = 0; j < 4; ++j)
        process4(tbl, a[j], base + j * THREADS, o4, out_s);
}

// Guarded variant for non-dividing sizes.
__global__ void __launch_bounds__(THREADS, 8) snn_tbl_kernel(
    const float4* __restrict__ x4, float4* __restrict__ o4, int nvec) {
    __shared__ unsigned tbl[2052];
    load_table(tbl);
    __syncthreads();

    const int base = blockIdx.x * VEC_PER_BLOCK + threadIdx.x;
    float* out_s = (float*)o4;

    float4 a[4];
    bool inb[4];
#pragma unroll
    for (int j = 0; j < 4; ++j) {
        int vi = base + j * THREADS;
        inb[j] = vi < nvec;
        a[j] = inb[j] ? x4[vi] : make_float4(1e9f, 1e9f, 1e9f, 1e9f);
    }
#pragma unroll
    for (int j = 0; j < 4; ++j) {
        if (inb[j]) process4(tbl, a[j], base + j * THREADS, o4, out_s);
    }
}

__global__ void snn_tail_kernel(const float* __restrict__ x,
                                float* __restrict__ o, int base, int n) {
    int i = base + blockIdx.x * blockDim.x + threadIdx.x;
    if (i < n) o[i] = snn_elem(x[i]);
}

extern "C" void kernel_launch(void* const* d_in, const int* in_sizes, int n_in,
                              void* d_out, int out_size) {
    const float* x = (const float*)d_in[0];
    float* out = (float*)d_out;
    int n = in_sizes[0];

    int nvec = n >> 2;
    if (nvec > 0) {
        if (nvec % VEC_PER_BLOCK == 0) {
            snn_tbl_full_kernel<<<nvec / VEC_PER_BLOCK, THREADS>>>(
                (const float4*)x, (float4*)out);
        } else {
            int blocks = (nvec + VEC_PER_BLOCK - 1) / VEC_PER_BLOCK;
            snn_tbl_kernel<<<blocks, THREADS>>>(
                (const float4*)x, (float4*)out, nvec);
        }
    }
    int rem = n & 3;
    if (rem > 0) {
        snn_tail_kernel<<<1, 32>>>(x, out, nvec << 2, n);
    }
}

// round 10
// speedup vs baseline: 1.0016x; 1.0016x over previous
#include <cuda_runtime.h>
#include <cstdint>

// ---------------------------------------------------------------------------
// Reference constants. Host constexpr copies (compile-time table generation)
// and __device__ copies (exact fallback path). Host constexpr fp32 +/-/* is
// IEEE RN => bit-identical to device FADD/FMUL.
// ---------------------------------------------------------------------------
constexpr float HH[16] = {
    -0.00443981f, 0.0244156f, -0.01410327f, 0.01784681f,
    -0.00239246f, 0.06331808f, 0.01457577f, 0.01753613f,
     0.01339214f, -0.0131252f, 0.02026613f, 0.00109124f,
    -0.01996419f, 0.00723148f, 0.03052537f, -0.00465259f};
constexpr float DDc[16] = {
    -0.04305673f, 2.0701091e-05f, -0.028386816f, 0.065610707f,
     0.071529418f, -0.0010542608f, 0.0012044241f, 0.00077212957f,
    -0.00072495628f, 0.0010990113f, 0.00087419833f, -0.0031887756f,
    -0.019837018f, 0.00030188679f, 0.00022616754f, -0.0017746047f};
constexpr float TTc[16] = {
    -0.1190194f, 0.03273299f, -0.05586114f, 0.07758415f,
    -0.06072911f, 0.04350465f, -0.06501344f, -0.07967568f,
    -0.08437239f, -0.07040057f, -0.07470815f, 0.01298669f,
     0.12695177f, 0.00617064f, -0.08909994f, 0.05016604f};

__device__ constexpr float cH[16] = {
    -0.00443981f, 0.0244156f, -0.01410327f, 0.01784681f,
    -0.00239246f, 0.06331808f, 0.01457577f, 0.01753613f,
     0.01339214f, -0.0131252f, 0.02026613f, 0.00109124f,
    -0.01996419f, 0.00723148f, 0.03052537f, -0.00465259f};
__device__ constexpr float cD[16] = {
    -0.04305673f, 2.0701091e-05f, -0.028386816f, 0.065610707f,
     0.071529418f, -0.0010542608f, 0.0012044241f, 0.00077212957f,
    -0.00072495628f, 0.0010990113f, 0.00087419833f, -0.0031887756f,
    -0.019837018f, 0.00030188679f, 0.00022616754f, -0.0017746047f};
__device__ constexpr float cT[16] = {
    -0.1190194f, 0.03273299f, -0.05586114f, 0.07758415f,
    -0.06072911f, 0.04350465f, -0.06501344f, -0.07967568f,
    -0.08437239f, -0.07040057f, -0.07470815f, 0.01298669f,
     0.12695177f, 0.00617064f, -0.08909994f, 0.05016604f};

// All-fire output in the reference's fp32 accumulation order.
constexpr float DSUM_C =
    (((((((((((((((-0.04305673f
      + 2.0701091e-05f) + -0.028386816f) + 0.065610707f) + 0.071529418f)
      + -0.0010542608f) + 0.0012044241f) + 0.00077212957f) + -0.00072495628f)
      + 0.0010990113f) + 0.00087419833f) + -0.0031887756f) + -0.019837018f)
      + 0.00030188679f) + 0.00022616754f) + -0.0017746047f);

constexpr int   NBUCKETS = 2048;
constexpr float KSCALE   = 2048.0f / 0.26f;   // all-fire for |x| >= 0.26
constexpr float SENTF    = 1e30f;             // sentinel (|outputs| < 1)

// Exact per-element trajectory (bit-identical to reference; rel_err==0
// since R0). (v-T)/(|v|+1) > 0 <=> v > T ; step 0 always fires (T[0]<0<=|x|).
__device__ __forceinline__ float snn_elem(float x) {
    float v = fabsf(x);
    float out = cD[0];
    v -= cH[1];
    bool z = v > cT[1];
    if (z) out += cD[1];
#pragma unroll
    for (int t = 2; t < 16; ++t) {
        if (z) v -= cH[t];
        z = v > cT[t];
        if (z) out += cD[t];
    }
    float r = (x > 0.0f) ? out : -out;
    return (x == 0.0f) ? 0.0f : r;
}

// ---------------------------------------------------------------------------
// Compile-time table. Bucket i covers u with trunc(fl(u*KSCALE)) == i.
// Endpoints widened by 1e-6 relative (covers the <=2^-24 slack of the fp32
// index product). fp32 monotonicity of the chain => equal firing patterns at
// both ends imply a constant, bit-exact output across the bucket; mismatch
// -> SENTF -> exact per-element fallback. (Validated rel_err==0 in R4-R9.)
// ---------------------------------------------------------------------------
constexpr unsigned snn_pat_ce(float u, float& out) {
    float v = u;
    out = DDc[0];
    unsigned mask = 1u;
    v -= HH[1];
    bool z = v > TTc[1];
    if (z) { out += DDc[1]; mask |= 2u; }
    for (int t = 2; t < 16; ++t) {
        if (z) v -= HH[t];
        z = v > TTc[t];
        if (z) { out += DDc[t]; mask |= (1u << t); }
    }
    return mask;
}

struct alignas(16) Table { float v[2052]; };

constexpr Table make_table() {
    Table tb{};
    tb.v[0] = SENTF;                          // bucket 0 contains x == +-0
    for (int i = 1; i < NBUCKETS; ++i) {
        float lo = (float)((double)i       / (double)KSCALE) * 0.999999f;
        float hi = (float)((double)(i + 1) / (double)KSCALE) * 1.000001f;
        float olo = 0.0f, ohi = 0.0f;
        unsigned mlo = snn_pat_ce(lo, olo);
        unsigned mhi = snn_pat_ce(hi, ohi);
        tb.v[i] = (mlo == mhi) ? olo : SENTF;
    }
    for (int i = NBUCKETS; i < 2052; ++i) tb.v[i] = DSUM_C;  // all-fire + pad
    return tb;
}

__device__ constexpr Table g_tbl = make_table();

// ---------------------------------------------------------------------------
// Main kernels — R8 launch configuration (best measured: 152.4us @ 81.8%
// DRAM; regs free, no min-block cap — R9 showed the reg cap costs ~2us and
// occupancy is NOT binding) + R9's aggregated sentinel check (1 branch per
// float4 instead of 4; no register cost). Plain LDG/STG (R6: .cs hints cost
// ~4% BW).
// ---------------------------------------------------------------------------
constexpr int THREADS       = 256;
constexpr int VEC_PER_BLOCK = 1024;    // 256 threads x 4 float4

__device__ __forceinline__ void load_table(unsigned* tbl) {
    const float4* src = reinterpret_cast<const float4*>(g_tbl.v);
    float4* dst = reinterpret_cast<float4*>(tbl);
#pragma unroll
    for (int k = 0; k < 3; ++k) {
        int t = threadIdx.x + k * THREADS;
        if (t < 513) dst[t] = src[t];
    }
}

__device__ __forceinline__ void process4(
    const unsigned* tbl, float4 aj, int vi,
    float4* __restrict__ o4, float* __restrict__ out_s) {
    const unsigned sent_bits = __float_as_uint(SENTF);
    const float xs[4] = {aj.x, aj.y, aj.z, aj.w};
    unsigned fb[4], rb[4];
#pragma unroll
    for (int c = 0; c < 4; ++c) {
        int idx = min((int)(fabsf(xs[c]) * KSCALE), NBUCKETS);
        fb[c] = tbl[idx];                     // LDS (~77% hit bucket 2048)
        rb[c] = (__float_as_uint(xs[c]) & 0x80000000u) ^ fb[c];
    }
    o4[vi] = make_float4(__uint_as_float(rb[0]), __uint_as_float(rb[1]),
                         __uint_as_float(rb[2]), __uint_as_float(rb[3]));
    // Aggregated rare-path check: one branch per float4. Sentinel hits
    // recompute exactly and overwrite their own placeholder (same thread,
    // program order).
    unsigned any_sent = (fb[0] == sent_bits) | (fb[1] == sent_bits) |
                        (fb[2] == sent_bits) | (fb[3] == sent_bits);
    if (any_sent) {
#pragma unroll
        for (int c = 0; c < 4; ++c) {
            if (fb[c] == sent_bits) out_s[vi * 4 + c] = snn_elem(xs[c]);
        }
    }
}

// Full blocks, no bounds checks. No min-block cap (R8 best config).
__global__ void __launch_bounds__(THREADS) snn_tbl_full_kernel(
    const float4* __restrict__ x4, float4* __restrict__ o4) {
    __shared__ unsigned tbl[2052];
    load_table(tbl);
    __syncthreads();

    const int base = blockIdx.x * VEC_PER_BLOCK + threadIdx.x;
    float* out_s = (float*)o4;

    float4 a[4];
#pragma unroll
    for (int j = 0; j < 4; ++j) a[j] = x4[base + j * THREADS];
#pragma unroll
    for (int j = 0; j < 4; ++j)
        process4(tbl, a[j], base + j * THREADS, o4, out_s);
}

// Guarded variant for non-dividing sizes.
__global__ void __launch_bounds__(THREADS) snn_tbl_kernel(
    const float4* __restrict__ x4, float4* __restrict__ o4, int nvec) {
    __shared__ unsigned tbl[2052];
    load_table(tbl);
    __syncthreads();

    const int base = blockIdx.x * VEC_PER_BLOCK + threadIdx.x;
    float* out_s = (float*)o4;

    float4 a[4];
    bool inb[4];
#pragma unroll
    for (int j = 0; j < 4; ++j) {
        int vi = base + j * THREADS;
        inb[j] = vi < nvec;
        a[j] = inb[j] ? x4[vi] : make_float4(1e9f, 1e9f, 1e9f, 1e9f);
    }
#pragma unroll
    for (int j = 0; j < 4; ++j) {
        if (inb[j]) process4(tbl, a[j], base + j * THREADS, o4, out_s);
    }
}

__global__ void snn_tail_kernel(const float* __restrict__ x,
                                float* __restrict__ o, int base, int n) {
    int i = base + blockIdx.x * blockDim.x + threadIdx.x;
    if (i < n) o[i] = snn_elem(x[i]);
}

extern "C" void kernel_launch(void* const* d_in, const int* in_sizes, int n_in,
                              void* d_out, int out_size) {
    const float* x = (const float*)d_in[0];
    float* out = (float*)d_out;
    int n = in_sizes[0];

    int nvec = n >> 2;
    if (nvec > 0) {
        if (nvec % VEC_PER_BLOCK == 0) {
            snn_tbl_full_kernel<<<nvec / VEC_PER_BLOCK, THREADS>>>(
                (const float4*)x, (float4*)out);
        } else {
            int blocks = (nvec + VEC_PER_BLOCK - 1) / VEC_PER_BLOCK;
            snn_tbl_kernel<<<blocks, THREADS>>>(
                (const float4*)x, (float4*)out, nvec);
        }
    }
    int rem = n & 3;
    if (rem > 0) {
        snn_tail_kernel<<<1, 32>>>(x, out, nvec << 2, n);
    }
}

// round 11
// speedup vs baseline: 1.0104x; 1.0088x over previous
#include <cuda_runtime.h>
#include <cstdint>

// ---------------------------------------------------------------------------
// FROZEN at R8 configuration — best measured: dur_us 160.1, main kernel
// 152.4us @ 81.8% DRAM (6.69 TB/s effective). R8/R9/R10 established a
// ~+-1.5us noise band at ~153us main across all remaining levers
// (occupancy, reg cap, sentinel aggregation): the kernel is at the
// achieved-bandwidth roofline for a 1:1 R/W fp32 stream on this part.
//
// Reference constants. Host constexpr copies (compile-time table generation)
// and __device__ copies (exact fallback path). Host constexpr fp32 +/-/* is
// IEEE RN => bit-identical to device FADD/FMUL.
// ---------------------------------------------------------------------------
constexpr float HH[16] = {
    -0.00443981f, 0.0244156f, -0.01410327f, 0.01784681f,
    -0.00239246f, 0.06331808f, 0.01457577f, 0.01753613f,
     0.01339214f, -0.0131252f, 0.02026613f, 0.00109124f,
    -0.01996419f, 0.00723148f, 0.03052537f, -0.00465259f};
constexpr float DDc[16] = {
    -0.04305673f, 2.0701091e-05f, -0.028386816f, 0.065610707f,
     0.071529418f, -0.0010542608f, 0.0012044241f, 0.00077212957f,
    -0.00072495628f, 0.0010990113f, 0.00087419833f, -0.0031887756f,
    -0.019837018f, 0.00030188679f, 0.00022616754f, -0.0017746047f};
constexpr float TTc[16] = {
    -0.1190194f, 0.03273299f, -0.05586114f, 0.07758415f,
    -0.06072911f, 0.04350465f, -0.06501344f, -0.07967568f,
    -0.08437239f, -0.07040057f, -0.07470815f, 0.01298669f,
     0.12695177f, 0.00617064f, -0.08909994f, 0.05016604f};

__device__ constexpr float cH[16] = {
    -0.00443981f, 0.0244156f, -0.01410327f, 0.01784681f,
    -0.00239246f, 0.06331808f, 0.01457577f, 0.01753613f,
     0.01339214f, -0.0131252f, 0.02026613f, 0.00109124f,
    -0.01996419f, 0.00723148f, 0.03052537f, -0.00465259f};
__device__ constexpr float cD[16] = {
    -0.04305673f, 2.0701091e-05f, -0.028386816f, 0.065610707f,
     0.071529418f, -0.0010542608f, 0.0012044241f, 0.00077212957f,
    -0.00072495628f, 0.0010990113f, 0.00087419833f, -0.0031887756f,
    -0.019837018f, 0.00030188679f, 0.00022616754f, -0.0017746047f};
__device__ constexpr float cT[16] = {
    -0.1190194f, 0.03273299f, -0.05586114f, 0.07758415f,
    -0.06072911f, 0.04350465f, -0.06501344f, -0.07967568f,
    -0.08437239f, -0.07040057f, -0.07470815f, 0.01298669f,
     0.12695177f, 0.00617064f, -0.08909994f, 0.05016604f};

// All-fire output in the reference's fp32 accumulation order.
constexpr float DSUM_C =
    (((((((((((((((-0.04305673f
      + 2.0701091e-05f) + -0.028386816f) + 0.065610707f) + 0.071529418f)
      + -0.0010542608f) + 0.0012044241f) + 0.00077212957f) + -0.00072495628f)
      + 0.0010990113f) + 0.00087419833f) + -0.0031887756f) + -0.019837018f)
      + 0.00030188679f) + 0.00022616754f) + -0.0017746047f);

constexpr int   NBUCKETS = 2048;
constexpr float KSCALE   = 2048.0f / 0.26f;   // all-fire for |x| >= 0.26
constexpr float SENTF    = 1e30f;             // sentinel (|outputs| < 1)

// Exact per-element trajectory (bit-identical to reference; rel_err==0
// since R0). (v-T)/(|v|+1) > 0 <=> v > T ; step 0 always fires (T[0]<0<=|x|).
__device__ __forceinline__ float snn_elem(float x) {
    float v = fabsf(x);
    float out = cD[0];
    v -= cH[1];
    bool z = v > cT[1];
    if (z) out += cD[1];
#pragma unroll
    for (int t = 2; t < 16; ++t) {
        if (z) v -= cH[t];
        z = v > cT[t];
        if (z) out += cD[t];
    }
    float r = (x > 0.0f) ? out : -out;
    return (x == 0.0f) ? 0.0f : r;
}

// ---------------------------------------------------------------------------
// Compile-time table. Bucket i covers u with trunc(fl(u*KSCALE)) == i.
// Endpoints widened by 1e-6 relative (covers the <=2^-24 slack of the fp32
// index product). fp32 monotonicity of the chain => equal firing patterns at
// both ends imply a constant, bit-exact output across the bucket; mismatch
// -> SENTF -> exact per-element fallback. (Validated rel_err==0 in R4-R10.)
// ---------------------------------------------------------------------------
constexpr unsigned snn_pat_ce(float u, float& out) {
    float v = u;
    out = DDc[0];
    unsigned mask = 1u;
    v -= HH[1];
    bool z = v > TTc[1];
    if (z) { out += DDc[1]; mask |= 2u; }
    for (int t = 2; t < 16; ++t) {
        if (z) v -= HH[t];
        z = v > TTc[t];
        if (z) { out += DDc[t]; mask |= (1u << t); }
    }
    return mask;
}

struct alignas(16) Table { float v[2052]; };

constexpr Table make_table() {
    Table tb{};
    tb.v[0] = SENTF;                          // bucket 0 contains x == +-0
    for (int i = 1; i < NBUCKETS; ++i) {
        float lo = (float)((double)i       / (double)KSCALE) * 0.999999f;
        float hi = (float)((double)(i + 1) / (double)KSCALE) * 1.000001f;
        float olo = 0.0f, ohi = 0.0f;
        unsigned mlo = snn_pat_ce(lo, olo);
        unsigned mhi = snn_pat_ce(hi, ohi);
        tb.v[i] = (mlo == mhi) ? olo : SENTF;
    }
    for (int i = NBUCKETS; i < 2052; ++i) tb.v[i] = DSUM_C;  // all-fire + pad
    return tb;
}

__device__ constexpr Table g_tbl = make_table();

// ---------------------------------------------------------------------------
// Main kernels — exact R8 code: 16 elements/thread, 4 float4 front-batched
// (MLP=4), plain LDG/STG (.cs hints cost ~4% BW, R6), per-element sentinel
// check, no reg cap, FULL variant (no bounds predication) when the grid
// divides exactly (true for the benchmark shape).
// ---------------------------------------------------------------------------
constexpr int THREADS       = 256;
constexpr int VEC_PER_BLOCK = 1024;    // 256 threads x 4 float4

__device__ __forceinline__ void load_table(unsigned* tbl) {
    const float4* src = reinterpret_cast<const float4*>(g_tbl.v);
    float4* dst = reinterpret_cast<float4*>(tbl);
#pragma unroll
    for (int k = 0; k < 3; ++k) {
        int t = threadIdx.x + k * THREADS;
        if (t < 513) dst[t] = src[t];
    }
}

__device__ __forceinline__ void process4(
    const unsigned* tbl, float4 aj, int vi,
    float4* __restrict__ o4, float* __restrict__ out_s) {
    const unsigned sent_bits = __float_as_uint(SENTF);
    const float xs[4] = {aj.x, aj.y, aj.z, aj.w};
    unsigned fb[4], rb[4];
#pragma unroll
    for (int c = 0; c < 4; ++c) {
        int idx = min((int)(fabsf(xs[c]) * KSCALE), NBUCKETS);
        fb[c] = tbl[idx];                     // LDS (~77% hit bucket 2048)
        rb[c] = (__float_as_uint(xs[c]) & 0x80000000u) ^ fb[c];
    }
    o4[vi] = make_float4(__uint_as_float(rb[0]), __uint_as_float(rb[1]),
                         __uint_as_float(rb[2]), __uint_as_float(rb[3]));
    // Rare exact fallback; overwrites own placeholder (same thread).
#pragma unroll
    for (int c = 0; c < 4; ++c) {
        if (fb[c] == sent_bits) out_s[vi * 4 + c] = snn_elem(xs[c]);
    }
}

// Full blocks, no bounds checks.
__global__ void __launch_bounds__(THREADS) snn_tbl_full_kernel(
    const float4* __restrict__ x4, float4* __restrict__ o4) {
    __shared__ unsigned tbl[2052];
    load_table(tbl);
    __syncthreads();

    const int base = blockIdx.x * VEC_PER_BLOCK + threadIdx.x;
    float* out_s = (float*)o4;

    float4 a[4];
#pragma unroll
    for (int j = 0; j < 4; ++j) a[j] = x4[base + j * THREADS];
#pragma unroll
    for (int j = 0; j < 4; ++j)
        process4(tbl, a[j], base + j * THREADS, o4, out_s);
}

// Guarded variant for non-dividing sizes.
__global__ void __launch_bounds__(THREADS) snn_tbl_kernel(
    const float4* __restrict__ x4, float4* __restrict__ o4, int nvec) {
    __shared__ unsigned tbl[2052];
    load_table(tbl);
    __syncthreads();

    const int base = blockIdx.x * VEC_PER_BLOCK + threadIdx.x;
    float* out_s = (float*)o4;

    float4 a[4];
    bool inb[4];
#pragma unroll
    for (int j = 0; j < 4; ++j) {
        int vi = base + j * THREADS;
        inb[j] = vi < nvec;
        a[j] = inb[j] ? x4[vi] : make_float4(1e9f, 1e9f, 1e9f, 1e9f);
    }
#pragma unroll
    for (int j = 0; j < 4; ++j) {
        if (inb[j]) process4(tbl, a[j], base + j * THREADS, o4, out_s);
    }
}

__global__ void snn_tail_kernel(const float* __restrict__ x,
                                float* __restrict__ o, int base, int n) {
    int i = base + blockIdx.x * blockDim.x + threadIdx.x;
    if (i < n) o[i] = snn_elem(x[i]);
}

extern "C" void kernel_launch(void* const* d_in, const int* in_sizes, int n_in,
                              void* d_out, int out_size) {
    const float* x = (const float*)d_in[0];
    float* out = (float*)d_out;
    int n = in_sizes[0];

    int nvec = n >> 2;
    if (nvec > 0) {
        if (nvec % VEC_PER_BLOCK == 0) {
            snn_tbl_full_kernel<<<nvec / VEC_PER_BLOCK, THREADS>>>(
                (const float4*)x, (float4*)out);
        } else {
            int blocks = (nvec + VEC_PER_BLOCK - 1) / VEC_PER_BLOCK;
            snn_tbl_kernel<<<blocks, THREADS>>>(
                (const float4*)x, (float4*)out, nvec);
        }
    }
    int rem = n & 3;
    if (rem > 0) {
        snn_tail_kernel<<<1, 32>>>(x, out, nvec << 2, n);
    }
}

// round 13
// speedup vs baseline: 1.0132x; 1.0028x over previous
#include <cuda_runtime.h>
#include <cstdint>

// ---------------------------------------------------------------------------
// R13: R12's config (THREADS 512, halved table-copy overhead + block count)
// with the R12 BUG FIXED: the table copy must cover 513 float4s; with 512
// threads that requires two strided iterations (R12 covered only 512 and
// left the all-fire bucket 2048 uninitialized -> rel_err 0.475).
//
// Reference constants. Host constexpr copies (compile-time table generation)
// and __device__ copies (exact fallback path). Host constexpr fp32 +/-/* is
// IEEE RN => bit-identical to device FADD/FMUL.
// ---------------------------------------------------------------------------
constexpr float HH[16] = {
    -0.00443981f, 0.0244156f, -0.01410327f, 0.01784681f,
    -0.00239246f, 0.06331808f, 0.01457577f, 0.01753613f,
     0.01339214f, -0.0131252f, 0.02026613f, 0.00109124f,
    -0.01996419f, 0.00723148f, 0.03052537f, -0.00465259f};
constexpr float DDc[16] = {
    -0.04305673f, 2.0701091e-05f, -0.028386816f, 0.065610707f,
     0.071529418f, -0.0010542608f, 0.0012044241f, 0.00077212957f,
    -0.00072495628f, 0.0010990113f, 0.00087419833f, -0.0031887756f,
    -0.019837018f, 0.00030188679f, 0.00022616754f, -0.0017746047f};
constexpr float TTc[16] = {
    -0.1190194f, 0.03273299f, -0.05586114f, 0.07758415f,
    -0.06072911f, 0.04350465f, -0.06501344f, -0.07967568f,
    -0.08437239f, -0.07040057f, -0.07470815f, 0.01298669f,
     0.12695177f, 0.00617064f, -0.08909994f, 0.05016604f};

__device__ constexpr float cH[16] = {
    -0.00443981f, 0.0244156f, -0.01410327f, 0.01784681f,
    -0.00239246f, 0.06331808f, 0.01457577f, 0.01753613f,
     0.01339214f, -0.0131252f, 0.02026613f, 0.00109124f,
    -0.01996419f, 0.00723148f, 0.03052537f, -0.00465259f};
__device__ constexpr float cD[16] = {
    -0.04305673f, 2.0701091e-05f, -0.028386816f, 0.065610707f,
     0.071529418f, -0.0010542608f, 0.0012044241f, 0.00077212957f,
    -0.00072495628f, 0.0010990113f, 0.00087419833f, -0.0031887756f,
    -0.019837018f, 0.00030188679f, 0.00022616754f, -0.0017746047f};
__device__ constexpr float cT[16] = {
    -0.1190194f, 0.03273299f, -0.05586114f, 0.07758415f,
    -0.06072911f, 0.04350465f, -0.06501344f, -0.07967568f,
    -0.08437239f, -0.07040057f, -0.07470815f, 0.01298669f,
     0.12695177f, 0.00617064f, -0.08909994f, 0.05016604f};

// All-fire output in the reference's fp32 accumulation order.
constexpr float DSUM_C =
    (((((((((((((((-0.04305673f
      + 2.0701091e-05f) + -0.028386816f) + 0.065610707f) + 0.071529418f)
      + -0.0010542608f) + 0.0012044241f) + 0.00077212957f) + -0.00072495628f)
      + 0.0010990113f) + 0.00087419833f) + -0.0031887756f) + -0.019837018f)
      + 0.00030188679f) + 0.00022616754f) + -0.0017746047f);

constexpr int   NBUCKETS = 2048;
constexpr float KSCALE   = 2048.0f / 0.26f;   // all-fire for |x| >= 0.26
constexpr float SENTF    = 1e30f;             // sentinel (|outputs| < 1)

// Exact per-element trajectory (bit-identical to reference; rel_err==0
// since R0). (v-T)/(|v|+1) > 0 <=> v > T ; step 0 always fires (T[0]<0<=|x|).
__device__ __forceinline__ float snn_elem(float x) {
    float v = fabsf(x);
    float out = cD[0];
    v -= cH[1];
    bool z = v > cT[1];
    if (z) out += cD[1];
#pragma unroll
    for (int t = 2; t < 16; ++t) {
        if (z) v -= cH[t];
        z = v > cT[t];
        if (z) out += cD[t];
    }
    float r = (x > 0.0f) ? out : -out;
    return (x == 0.0f) ? 0.0f : r;
}

// ---------------------------------------------------------------------------
// Compile-time table. Bucket i covers u with trunc(fl(u*KSCALE)) == i.
// Endpoints widened by 1e-6 relative (covers the <=2^-24 slack of the fp32
// index product). fp32 monotonicity of the chain => equal firing patterns at
// both ends imply a constant, bit-exact output across the bucket; mismatch
// -> SENTF -> exact per-element fallback. (Validated rel_err==0 in R4-R11.)
// ---------------------------------------------------------------------------
constexpr unsigned snn_pat_ce(float u, float& out) {
    float v = u;
    out = DDc[0];
    unsigned mask = 1u;
    v -= HH[1];
    bool z = v > TTc[1];
    if (z) { out += DDc[1]; mask |= 2u; }
    for (int t = 2; t < 16; ++t) {
        if (z) v -= HH[t];
        z = v > TTc[t];
        if (z) { out += DDc[t]; mask |= (1u << t); }
    }
    return mask;
}

struct alignas(16) Table { float v[2052]; };

constexpr Table make_table() {
    Table tb{};
    tb.v[0] = SENTF;                          // bucket 0 contains x == +-0
    for (int i = 1; i < NBUCKETS; ++i) {
        float lo = (float)((double)i       / (double)KSCALE) * 0.999999f;
        float hi = (float)((double)(i + 1) / (double)KSCALE) * 1.000001f;
        float olo = 0.0f, ohi = 0.0f;
        unsigned mlo = snn_pat_ce(lo, olo);
        unsigned mhi = snn_pat_ce(hi, ohi);
        tb.v[i] = (mlo == mhi) ? olo : SENTF;
    }
    for (int i = NBUCKETS; i < 2052; ++i) tb.v[i] = DSUM_C;  // all-fire + pad
    return tb;
}

__device__ constexpr Table g_tbl = make_table();

// ---------------------------------------------------------------------------
// Main kernels: 512 threads, 4 float4 front-batched per thread (MLP=4),
// plain LDG/STG (.cs costs ~4% BW, R6), per-element sentinel check, no reg
// cap. FULL variant (no bounds predication) when the grid divides exactly.
// ---------------------------------------------------------------------------
constexpr int THREADS       = 512;
constexpr int VEC_PER_BLOCK = 2048;    // 512 threads x 4 float4

__device__ __forceinline__ void load_table(unsigned* tbl) {
    const float4* src = reinterpret_cast<const float4*>(g_tbl.v);
    float4* dst = reinterpret_cast<float4*>(tbl);
    // 513 float4s with 512 threads: two strided iterations (R12 bug fix —
    // a single pass left float4 #512, i.e. the all-fire bucket 2048, uncopied).
#pragma unroll
    for (int k = 0; k < 2; ++k) {
        int t = threadIdx.x + k * THREADS;
        if (t < 513) dst[t] = src[t];
    }
}

__device__ __forceinline__ void process4(
    const unsigned* tbl, float4 aj, int vi,
    float4* __restrict__ o4, float* __restrict__ out_s) {
    const unsigned sent_bits = __float_as_uint(SENTF);
    const float xs[4] = {aj.x, aj.y, aj.z, aj.w};
    unsigned fb[4], rb[4];
#pragma unroll
    for (int c = 0; c < 4; ++c) {
        int idx = min((int)(fabsf(xs[c]) * KSCALE), NBUCKETS);
        fb[c] = tbl[idx];                     // LDS (~77% hit bucket 2048)
        rb[c] = (__float_as_uint(xs[c]) & 0x80000000u) ^ fb[c];
    }
    o4[vi] = make_float4(__uint_as_float(rb[0]), __uint_as_float(rb[1]),
                         __uint_as_float(rb[2]), __uint_as_float(rb[3]));
    // Rare exact fallback; overwrites own placeholder (same thread).
#pragma unroll
    for (int c = 0; c < 4; ++c) {
        if (fb[c] == sent_bits) out_s[vi * 4 + c] = snn_elem(xs[c]);
    }
}

// Full blocks, no bounds checks.
__global__ void __launch_bounds__(THREADS) snn_tbl_full_kernel(
    const float4* __restrict__ x4, float4* __restrict__ o4) {
    __shared__ unsigned tbl[2052];
    load_table(tbl);
    __syncthreads();

    const int base = blockIdx.x * VEC_PER_BLOCK + threadIdx.x;
    float* out_s = (float*)o4;

    float4 a[4];
#pragma unroll
    for (int j = 0; j < 4; ++j) a[j] = x4[base + j * THREADS];
#pragma unroll
    for (int j = 0; j < 4; ++j)
        process4(tbl, a[j], base + j * THREADS, o4, out_s);
}

// Guarded variant for non-dividing sizes.
__global__ void __launch_bounds__(THREADS) snn_tbl_kernel(
    const float4* __restrict__ x4, float4* __restrict__ o4, int nvec) {
    __shared__ unsigned tbl[2052];
    load_table(tbl);
    __syncthreads();

    const int base = blockIdx.x * VEC_PER_BLOCK + threadIdx.x;
    float* out_s = (float*)o4;

    float4 a[4];
    bool inb[4];
#pragma unroll
    for (int j = 0; j < 4; ++j) {
        int vi = base + j * THREADS;
        inb[j] = vi < nvec;
        a[j] = inb[j] ? x4[vi] : make_float4(1e9f, 1e9f, 1e9f, 1e9f);
    }
#pragma unroll
    for (int j = 0; j < 4; ++j) {
        if (inb[j]) process4(tbl, a[j], base + j * THREADS, o4, out_s);
    }
}

__global__ void snn_tail_kernel(const float* __restrict__ x,
                                float* __restrict__ o, int base, int n) {
    int i = base + blockIdx.x * blockDim.x + threadIdx.x;
    if (i < n) o[i] = snn_elem(x[i]);
}

extern "C" void kernel_launch(void* const* d_in, const int* in_sizes, int n_in,
                              void* d_out, int out_size) {
    const float* x = (const float*)d_in[0];
    float* out = (float*)d_out;
    int n = in_sizes[0];

    int nvec = n >> 2;
    if (nvec > 0) {
        if (nvec % VEC_PER_BLOCK == 0) {
            snn_tbl_full_kernel<<<nvec / VEC_PER_BLOCK, THREADS>>>(
                (const float4*)x, (float4*)out);
        } else {
            int blocks = (nvec + VEC_PER_BLOCK - 1) / VEC_PER_BLOCK;
            snn_tbl_kernel<<<blocks, THREADS>>>(
                (const float4*)x, (float4*)out, nvec);
        }
    }
    int rem = n & 3;
    if (rem > 0) {
        snn_tail_kernel<<<1, 32>>>(x, out, nvec << 2, n);
    }
}